// round 2
// baseline (speedup 1.0000x reference)
#include <cuda_runtime.h>
#include <math.h>

#define M_ROWS   65536
#define D_DIM    64
#define K_CODES  4096
#define TK       128
#define NTILES   (K_CODES / TK)
#define MAIN_BLOCK 512
#define MAIN_GRID  (M_ROWS / MAIN_BLOCK)   // 128

// Scratch (no allocations allowed in kernel_launch)
__device__ float g_c[K_CODES];           // 0.5 * ||e_k||^2
__device__ float g_partials[MAIN_GRID];  // per-CTA commit-loss partial sums

// ---------- packed f32x2 helpers (SASS FFMA2 path, PTX-only) ----------
__device__ __forceinline__ void fma2(unsigned long long& d,
                                     unsigned long long a,
                                     unsigned long long b) {
    asm("fma.rn.f32x2 %0, %1, %2, %0;" : "+l"(d) : "l"(a), "l"(b));
}
__device__ __forceinline__ unsigned long long add2(unsigned long long a,
                                                   unsigned long long b) {
    unsigned long long r;
    asm("add.rn.f32x2 %0, %1, %2;" : "=l"(r) : "l"(a), "l"(b));
    return r;
}
__device__ __forceinline__ float2 unpack2(unsigned long long v) {
    float2 f;
    asm("mov.b64 {%0, %1}, %2;" : "=f"(f.x), "=f"(f.y) : "l"(v));
    return f;
}

// ---------- kernel 1: c_k = 0.5 * ||e_k||^2, one warp per code ----------
__global__ void vq_calc_c_kernel(const float* __restrict__ cb) {
    int k    = blockIdx.x * 8 + (threadIdx.x >> 5);
    int lane = threadIdx.x & 31;
    float2 v = reinterpret_cast<const float2*>(cb + (size_t)k * D_DIM)[lane];
    float s  = v.x * v.x + v.y * v.y;
    #pragma unroll
    for (int o = 16; o > 0; o >>= 1) s += __shfl_down_sync(0xffffffffu, s, o);
    if (lane == 0) g_c[k] = 0.5f * s;
}

// ---------- kernel 2: fused GEMM + argmin + gather + loss partials ----------
__global__ void __launch_bounds__(MAIN_BLOCK, 1)
vq_main_kernel(const float* __restrict__ z_e,
               const float* __restrict__ cb,
               float* __restrict__ out,
               int out_size_i) {
    __shared__ float sh[TK * D_DIM];   // 32 KB codebook tile
    __shared__ float shc[TK];          // 0.5*||e||^2 for tile
    __shared__ float shred[16];        // warp partials for loss

    const size_t osz = (size_t)out_size_i;
    const int tid = threadIdx.x;
    const int m   = blockIdx.x * MAIN_BLOCK + tid;

    // z row -> 32 packed u64 registers (LDG.128)
    unsigned long long zp[32];
    {
        const ulonglong2* zr =
            reinterpret_cast<const ulonglong2*>(z_e + (size_t)m * D_DIM);
        #pragma unroll
        for (int i = 0; i < 16; i++) {
            ulonglong2 v = zr[i];
            zp[2 * i]     = v.x;
            zp[2 * i + 1] = v.y;
        }
    }

    float best = -1e38f;
    int   bi   = 0;
    const float4* cb4 = reinterpret_cast<const float4*>(cb);

    for (int kt = 0; kt < NTILES; kt++) {
        __syncthreads();
        // stage codebook tile: TK*64 floats = 2048 float4
        #pragma unroll
        for (int i = tid; i < TK * (D_DIM / 4); i += MAIN_BLOCK)
            reinterpret_cast<float4*>(sh)[i] = cb4[kt * TK * (D_DIM / 4) + i];
        if (tid < TK) shc[tid] = g_c[kt * TK + tid];
        __syncthreads();

        #pragma unroll 2
        for (int kk = 0; kk < TK; kk++) {
            const ulonglong2* er =
                reinterpret_cast<const ulonglong2*>(sh + kk * D_DIM);
            unsigned long long a0 = 0ull, a1 = 0ull, a2 = 0ull, a3 = 0ull;
            #pragma unroll
            for (int i = 0; i < 16; i++) {
                ulonglong2 v = er[i];   // broadcast LDS.128 (N=1, conflict-free)
                if (i & 1) { fma2(a2, zp[2 * i], v.x); fma2(a3, zp[2 * i + 1], v.y); }
                else       { fma2(a0, zp[2 * i], v.x); fma2(a1, zp[2 * i + 1], v.y); }
            }
            a0 = add2(a0, a2);
            a1 = add2(a1, a3);
            a0 = add2(a0, a1);
            float2 f = unpack2(a0);
            float s  = (f.x + f.y) - shc[kk];
            if (s > best) { best = s; bi = kt * TK + kk; }  // strict > keeps first index (argmin tie rule)
        }
    }

    // ---- epilogue: gather chosen code, write outputs, loss partial ----
    const size_t MD    = (size_t)M_ROWS * D_DIM;
    const size_t base2 = MD + M_ROWS + 2;           // start of z_q region
    const float4* er = reinterpret_cast<const float4*>(cb + (size_t)bi * D_DIM);
    float lsum = 0.0f;

    float4* out4 = reinterpret_cast<float4*>(out);
    float2* out2 = reinterpret_cast<float2*>(out);
    const size_t o1 = (size_t)m * D_DIM;            // z_q_st offset (16B aligned)
    const size_t o3 = base2 + (size_t)m * D_DIM;    // z_q offset (8B aligned)

    #pragma unroll
    for (int i = 0; i < 16; i++) {
        float4 e  = er[i];
        float2 z0 = unpack2(zp[2 * i]);
        float2 z1 = unpack2(zp[2 * i + 1]);

        // straight-through: z + (e - z), same rounding as reference
        float4 zst;
        zst.x = z0.x + (e.x - z0.x);
        zst.y = z0.y + (e.y - z0.y);
        zst.z = z1.x + (e.z - z1.x);
        zst.w = z1.y + (e.w - z1.y);

        float d0 = z0.x - e.x, d1 = z0.y - e.y, d2 = z1.x - e.z, d3 = z1.y - e.w;
        lsum += d0 * d0 + d1 * d1 + d2 * d2 + d3 * d3;

        if (o1 + (size_t)i * 4 + 4 <= osz) out4[o1 / 4 + i] = zst;
        if (o3 + (size_t)i * 4 + 4 <= osz) {
            float2 ea = make_float2(e.x, e.y);
            float2 eb = make_float2(e.z, e.w);
            out2[o3 / 2 + 2 * i]     = ea;
            out2[o3 / 2 + 2 * i + 1] = eb;
        }
    }
    if (MD + (size_t)m < osz) out[MD + (size_t)m] = (float)bi;

    // deterministic per-CTA loss reduction
    #pragma unroll
    for (int o = 16; o > 0; o >>= 1) lsum += __shfl_down_sync(0xffffffffu, lsum, o);
    if ((tid & 31) == 0) shred[tid >> 5] = lsum;
    __syncthreads();
    if (tid == 0) {
        float t = 0.0f;
        #pragma unroll
        for (int i = 0; i < MAIN_BLOCK / 32; i++) t += shred[i];
        g_partials[blockIdx.x] = t;
    }
}

// ---------- kernel 3: finalize vq_loss + perplexity ----------
__global__ void vq_finalize_kernel(const float* __restrict__ ema,
                                   float* __restrict__ out,
                                   int out_size_i) {
    __shared__ float red[1024];
    const size_t osz = (size_t)out_size_i;
    const int tid = threadIdx.x;

    // commit loss: sum the 128 CTA partials (fixed-order tree -> deterministic)
    float v = (tid < MAIN_GRID) ? g_partials[tid] : 0.0f;
    red[tid] = v;
    for (int o = 512; o > 0; o >>= 1) {
        __syncthreads();
        if (tid < o) red[tid] += red[tid + o];
    }
    __syncthreads();
    const float vq_loss = 0.25f * red[0] / (float)((size_t)M_ROWS * D_DIM);
    __syncthreads();

    // perplexity from ema_cluster_size
    float s = 0.0f;
    for (int i = tid; i < K_CODES; i += 1024) s += ema[i] + 1e-10f;
    red[tid] = s;
    for (int o = 512; o > 0; o >>= 1) {
        __syncthreads();
        if (tid < o) red[tid] += red[tid + o];
    }
    __syncthreads();
    const float S = red[0];
    __syncthreads();

    float ent = 0.0f;
    for (int i = tid; i < K_CODES; i += 1024) {
        float p = (ema[i] + 1e-10f) / S;
        ent += p * logf(p);
    }
    red[tid] = ent;
    for (int o = 512; o > 0; o >>= 1) {
        __syncthreads();
        if (tid < o) red[tid] += red[tid + o];
    }
    __syncthreads();

    if (tid == 0) {
        const size_t base = (size_t)M_ROWS * D_DIM + M_ROWS;
        if (base < osz)     out[base]     = vq_loss;
        if (base + 1 < osz) out[base + 1] = expf(-red[0]);
    }
}

extern "C" void kernel_launch(void* const* d_in, const int* in_sizes, int n_in,
                              void* d_out, int out_size) {
    const float* z_e = (const float*)d_in[0];   // (65536, 64) f32
    const float* cb  = (const float*)d_in[1];   // (4096, 64) f32
    const float* ema = (const float*)d_in[2];   // (4096,) f32
    float* out = (float*)d_out;

    vq_calc_c_kernel<<<K_CODES / 8, 256>>>(cb);
    vq_main_kernel<<<MAIN_GRID, MAIN_BLOCK>>>(z_e, cb, out, out_size);
    vq_finalize_kernel<<<1, 1024>>>(ema, out, out_size);
}

// round 4
// speedup vs baseline: 3.7252x; 3.7252x over previous
#include <cuda_runtime.h>
#include <cuda_bf16.h>
#include <math.h>

#define M_ROWS   65536
#define D_DIM    64
#define K_CODES  4096
#define KS       216                      // padded K stride (bf16 elems), 208 used
#define MT       128                      // rows per CTA
#define NT       128                      // codes per chunk
#define NCH      (K_CODES / NT)           // 32
#define MTILES   (M_ROWS / MT)            // 512
#define TILE_BYTES (MT * KS * 2)          // 55296 (A tile == B chunk size)
#define CP_UNITS   (TILE_BYTES / 16)      // 3456
#define SMEM_DYN   (3 * TILE_BYTES)       // A + 2x B

// ---- global scratch (static __device__; no runtime allocs) ----
__device__ __align__(16) unsigned char g_A[(size_t)M_ROWS * KS * 2];   // ~28 MB
__device__ __align__(16) unsigned char g_B[(size_t)K_CODES * KS * 2];  // ~1.8 MB
__device__ float g_c[K_CODES];                                         // 0.5*||e||^2
__device__ float g_partials[MTILES];

// ======================= helpers (compute_103-safe) =======================
__device__ __forceinline__ unsigned smem_u32(const void* p) {
    unsigned a;
    asm("{ .reg .u64 t; cvta.to.shared.u64 t, %1; cvt.u32.u64 %0, t; }" : "=r"(a) : "l"(p));
    return a;
}
__device__ __forceinline__ unsigned pack_bf16x2(float lo, float hi) {
    unsigned r;
    asm("cvt.rn.bf16x2.f32 %0, %1, %2;" : "=r"(r) : "f"(hi), "f"(lo));
    return r;  // low 16 bits (first in memory) = lo
}
__device__ __forceinline__ void cp_async16(unsigned saddr, const void* gaddr) {
    asm volatile("cp.async.cg.shared.global [%0], [%1], 16;" :: "r"(saddr), "l"(gaddr) : "memory");
}
__device__ __forceinline__ void cp_commit() {
    asm volatile("cp.async.commit_group;" ::: "memory");
}
template <int N>
__device__ __forceinline__ void cp_wait() {
    asm volatile("cp.async.wait_group %0;" :: "n"(N) : "memory");
}
__device__ __forceinline__ void ldsm_x4(unsigned* r, unsigned addr) {
    asm volatile("ldmatrix.sync.aligned.m8n8.x4.shared.b16 {%0,%1,%2,%3}, [%4];"
                 : "=r"(r[0]), "=r"(r[1]), "=r"(r[2]), "=r"(r[3]) : "r"(addr));
}
__device__ __forceinline__ void mma16816(float* c, const unsigned* a, const unsigned* b) {
    asm volatile(
        "mma.sync.aligned.m16n8k16.row.col.f32.bf16.bf16.f32 "
        "{%0,%1,%2,%3}, {%4,%5,%6,%7}, {%8,%9}, {%0,%1,%2,%3};"
        : "+f"(c[0]), "+f"(c[1]), "+f"(c[2]), "+f"(c[3])
        : "r"(a[0]), "r"(a[1]), "r"(a[2]), "r"(a[3]), "r"(b[0]), "r"(b[1]));
}
__device__ __forceinline__ void upd2(float& b, float& s, int& bi, int& si, float v, int c) {
    bool g1 = v > b;
    bool g2 = v > s;
    s  = g1 ? b  : (g2 ? v : s);
    si = g1 ? bi : (g2 ? c : si);
    b  = g1 ? v : b;
    bi = g1 ? c : bi;
}
// merge two top-2 sets across lanes via shfl.bfly (tie -> smaller index)
__device__ __forceinline__ void merge2(float& best, float& sec, int& bi, int& si, int off) {
    float ob  = __shfl_xor_sync(0xffffffffu, best, off);
    int   oi  = __shfl_xor_sync(0xffffffffu, bi,   off);
    float os  = __shfl_xor_sync(0xffffffffu, sec,  off);
    int   osi = __shfl_xor_sync(0xffffffffu, si,   off);
    bool take = (ob > best) || (ob == best && oi < bi);
    float nb  = take ? ob : best;  int nbi = take ? oi : bi;
    float c1  = take ? best : ob;  int c1i = take ? bi : oi;
    float c2  = take ? os : sec;   int c2i = take ? osi : si;
    bool t2   = (c2 > c1) || (c2 == c1 && c2i < c1i);
    sec  = t2 ? c2 : c1;  si = t2 ? c2i : c1i;
    best = nb;            bi = nbi;
}

// ===================== prep kernels =====================
__global__ void vq_prep_c(const float* __restrict__ cb) {
    int k    = blockIdx.x * 8 + (threadIdx.x >> 5);
    int lane = threadIdx.x & 31;
    float2 v = reinterpret_cast<const float2*>(cb + (size_t)k * D_DIM)[lane];
    float s  = v.x * v.x + v.y * v.y;
    #pragma unroll
    for (int o = 16; o > 0; o >>= 1) s += __shfl_down_sync(0xffffffffu, s, o);
    if (lane == 0) g_c[k] = 0.5f * s;
}

// A row m: [z_hi(0:64) | z_lo(64:128) | z_hi(128:192) | 1,1 @192,193 | 0 pad]
__global__ void vq_prep_A(const float* __restrict__ z) {
    int m = blockIdx.x * 8 + (threadIdx.x >> 5);
    int l = threadIdx.x & 31;
    float2 x = reinterpret_cast<const float2*>(z + (size_t)m * D_DIM)[l];
    float hx = __bfloat162float(__float2bfloat16(x.x));
    float hy = __bfloat162float(__float2bfloat16(x.y));
    unsigned H = pack_bf16x2(x.x, x.y);
    unsigned L = pack_bf16x2(x.x - hx, x.y - hy);
    unsigned* row = reinterpret_cast<unsigned*>(g_A) + (size_t)m * (KS / 2);
    row[l] = H; row[32 + l] = L; row[64 + l] = H;
    if (l == 0) row[96] = pack_bf16x2(1.0f, 1.0f);
    if (l >= 1 && l <= 11) row[96 + l] = 0u;
}

// B row k: [e_hi | e_hi | e_lo | -c_hi,-c_lo @192,193 | 0 pad]
__global__ void vq_prep_B(const float* __restrict__ cb) {
    int k = blockIdx.x * 8 + (threadIdx.x >> 5);
    int l = threadIdx.x & 31;
    float2 x = reinterpret_cast<const float2*>(cb + (size_t)k * D_DIM)[l];
    float hx = __bfloat162float(__float2bfloat16(x.x));
    float hy = __bfloat162float(__float2bfloat16(x.y));
    unsigned H = pack_bf16x2(x.x, x.y);
    unsigned L = pack_bf16x2(x.x - hx, x.y - hy);
    unsigned* row = reinterpret_cast<unsigned*>(g_B) + (size_t)k * (KS / 2);
    row[l] = H; row[32 + l] = H; row[64 + l] = L;
    if (l == 0) {
        float c  = g_c[k];
        float ch = __bfloat162float(__float2bfloat16(c));
        row[96] = pack_bf16x2(-ch, -(c - ch));
    }
    if (l >= 1 && l <= 11) row[96 + l] = 0u;
}

// ===================== main fused HMMA GEMM + argmax =====================
__global__ void __launch_bounds__(256, 1)
vq_mma_kernel(float* __restrict__ out, const float* __restrict__ z_e,
              const float* __restrict__ cb, int out_size_i) {
    extern __shared__ unsigned char smem_raw[];
    __shared__ float shred[8];

    const unsigned uA  = smem_u32(smem_raw);
    const unsigned uB0 = uA + TILE_BYTES;
    const unsigned uB1 = uB0 + TILE_BYTES;

    const int tid = threadIdx.x;
    const int w   = tid >> 5;
    const int l   = tid & 31;
    const int tile = blockIdx.x;

    // ---- prologue: A tile + B chunk 0 (one cp.async group) ----
    {
        const unsigned char* gA = g_A + (size_t)tile * TILE_BYTES;
        for (int u = tid; u < CP_UNITS; u += 256) cp_async16(uA + u * 16, gA + u * 16);
        for (int u = tid; u < CP_UNITS; u += 256) cp_async16(uB0 + u * 16, g_B + u * 16);
        cp_commit();
    }

    // per-lane ldmatrix offsets
    // A (m16k16 x4): quads [rows0-7,k0-7][rows8-15,k0-7][rows0-7,k8-15][rows8-15,k8-15]
    const unsigned aoff = ((w * 16 + (l & 7) + ((l >> 3) & 1) * 8) * KS + (l >> 4) * 8) * 2;
    // B (n16k16 x4): quads [n0-7,k0-7][n0-7,k8-15][n8-15,k0-7][n8-15,k8-15]
    const unsigned boff = (((l >> 4) * 8 + (l & 7)) * KS + ((l >> 3) & 1) * 8) * 2;

    float acc[64];
    #pragma unroll
    for (int i = 0; i < 64; i++) acc[i] = 0.0f;
    float best0 = -3.402823466e38f, sec0 = -3.402823466e38f;
    float best1 = -3.402823466e38f, sec1 = -3.402823466e38f;
    int bi0 = 0, si0 = 0, bi1 = 0, si1 = 0;

    for (int ch = 0; ch < NCH; ch++) {
        const unsigned ub = (ch & 1) ? uB1 : uB0;
        if (ch + 1 < NCH) {
            const unsigned ubn = (ch & 1) ? uB0 : uB1;
            const unsigned char* gBn = g_B + (size_t)(ch + 1) * TILE_BYTES;
            for (int u = tid; u < CP_UNITS; u += 256) cp_async16(ubn + u * 16, gBn + u * 16);
            cp_commit();
            cp_wait<1>();
        } else {
            cp_wait<0>();
        }
        __syncthreads();

        #pragma unroll
        for (int s = 0; s < 13; s++) {
            unsigned a[4];
            ldsm_x4(a, uA + aoff + s * 32);
            #pragma unroll
            for (int p = 0; p < 8; p++) {
                unsigned b[4];
                ldsm_x4(b, ub + boff + (unsigned)p * (16 * KS * 2) + s * 32);
                mma16816(&acc[(2 * p) * 4],     a, b);
                mma16816(&acc[(2 * p + 1) * 4], a, b + 2);
            }
        }

        // fold 64 scores into per-lane top-2 (cols ascend -> strict > keeps first index)
        const int cbase = ch * NT + 2 * (l & 3);
        #pragma unroll
        for (int f = 0; f < 16; f++) {
            const int c0 = cbase + f * 8;
            upd2(best0, sec0, bi0, si0, acc[f * 4 + 0], c0);
            upd2(best0, sec0, bi0, si0, acc[f * 4 + 1], c0 + 1);
            upd2(best1, sec1, bi1, si1, acc[f * 4 + 2], c0);
            upd2(best1, sec1, bi1, si1, acc[f * 4 + 3], c0 + 1);
            acc[f * 4 + 0] = 0.0f; acc[f * 4 + 1] = 0.0f;
            acc[f * 4 + 2] = 0.0f; acc[f * 4 + 3] = 0.0f;
        }
        __syncthreads();   // all reads of this buffer done before next prefetch overwrites
    }

    // ---- cross-lane merge within each quad (lanes differing in tig bits) ----
    merge2(best0, sec0, bi0, si0, 1); merge2(best0, sec0, bi0, si0, 2);
    merge2(best1, sec1, bi1, si1, 1); merge2(best1, sec1, bi1, si1, 2);

    // per-row results -> smem (alias A region; safe after final sync)
    float* s_b  = reinterpret_cast<float*>(smem_raw);
    float* s_s  = s_b + 128;
    int*   s_bi = reinterpret_cast<int*>(s_b + 256);
    int*   s_si = s_bi + 128;
    if ((l & 3) == 0) {
        const int g = l >> 2;
        const int r0 = w * 16 + g, r1 = r0 + 8;
        s_b[r0] = best0; s_s[r0] = sec0; s_bi[r0] = bi0; s_si[r0] = si0;
        s_b[r1] = best1; s_s[r1] = sec1; s_bi[r1] = bi1; s_si[r1] = si1;
    }
    __syncthreads();

    // ---- exact fp32 rescore of top-2, gather, outputs, loss ----
    const size_t osz = (size_t)out_size_i;
    float lsum = 0.0f;
    if (tid < 128) {
        const int m    = tile * MT + tid;
        const int bidx = s_bi[tid];
        const int sidx = s_si[tid];
        const float4* zr = reinterpret_cast<const float4*>(z_e + (size_t)m * D_DIM);
        const float4* eb = reinterpret_cast<const float4*>(cb + (size_t)bidx * D_DIM);
        const float4* es = reinterpret_cast<const float4*>(cb + (size_t)sidx * D_DIM);
        float sb = -g_c[bidx], ss = -g_c[sidx];
        #pragma unroll
        for (int j = 0; j < 16; j++) {
            float4 zz = zr[j], b = eb[j], s2 = es[j];
            sb += zz.x * b.x + zz.y * b.y + zz.z * b.z + zz.w * b.w;
            ss += zz.x * s2.x + zz.y * s2.y + zz.z * s2.z + zz.w * s2.w;
        }
        const int fin = (ss > sb || (ss == sb && sidx < bidx)) ? sidx : bidx;

        const size_t MD    = (size_t)M_ROWS * D_DIM;
        const size_t base2 = MD + M_ROWS + 2;
        const float4* er = reinterpret_cast<const float4*>(cb + (size_t)fin * D_DIM);
        float4* out4 = reinterpret_cast<float4*>(out);
        float2* out2 = reinterpret_cast<float2*>(out);
        const size_t o1 = (size_t)m * D_DIM;
        const size_t o3 = base2 + (size_t)m * D_DIM;

        #pragma unroll
        for (int j = 0; j < 16; j++) {
            float4 e = er[j];
            float4 z = zr[j];
            float4 zst;
            zst.x = z.x + (e.x - z.x);
            zst.y = z.y + (e.y - z.y);
            zst.z = z.z + (e.z - z.z);
            zst.w = z.w + (e.w - z.w);
            float d0 = z.x - e.x, d1 = z.y - e.y, d2 = z.z - e.z, d3 = z.w - e.w;
            lsum += d0 * d0 + d1 * d1 + d2 * d2 + d3 * d3;
            if (o1 + (size_t)j * 4 + 4 <= osz) out4[o1 / 4 + j] = zst;
            if (o3 + (size_t)j * 4 + 4 <= osz) {
                out2[o3 / 2 + 2 * j]     = make_float2(e.x, e.y);
                out2[o3 / 2 + 2 * j + 1] = make_float2(e.z, e.w);
            }
        }
        if (MD + (size_t)m < osz) out[MD + (size_t)m] = (float)fin;
    }

    #pragma unroll
    for (int o = 16; o > 0; o >>= 1) lsum += __shfl_down_sync(0xffffffffu, lsum, o);
    if ((tid & 31) == 0) shred[w] = lsum;
    __syncthreads();
    if (tid == 0) {
        float t = 0.0f;
        #pragma unroll
        for (int i = 0; i < 8; i++) t += shred[i];
        g_partials[tile] = t;
    }
}

// ===================== finalize: vq_loss + perplexity =====================
__global__ void vq_finalize_kernel(const float* __restrict__ ema,
                                   float* __restrict__ out, int out_size_i) {
    __shared__ float red[1024];
    const size_t osz = (size_t)out_size_i;
    const int tid = threadIdx.x;

    float v = (tid < MTILES) ? g_partials[tid] : 0.0f;
    red[tid] = v;
    for (int o = 512; o > 0; o >>= 1) {
        __syncthreads();
        if (tid < o) red[tid] += red[tid + o];
    }
    __syncthreads();
    const float vq_loss = 0.25f * red[0] / (float)((size_t)M_ROWS * D_DIM);
    __syncthreads();

    float s = 0.0f;
    for (int i = tid; i < K_CODES; i += 1024) s += ema[i] + 1e-10f;
    red[tid] = s;
    for (int o = 512; o > 0; o >>= 1) {
        __syncthreads();
        if (tid < o) red[tid] += red[tid + o];
    }
    __syncthreads();
    const float S = red[0];
    __syncthreads();

    float ent = 0.0f;
    for (int i = tid; i < K_CODES; i += 1024) {
        float p = (ema[i] + 1e-10f) / S;
        ent += p * logf(p);
    }
    red[tid] = ent;
    for (int o = 512; o > 0; o >>= 1) {
        __syncthreads();
        if (tid < o) red[tid] += red[tid + o];
    }
    __syncthreads();

    if (tid == 0) {
        const size_t base = (size_t)M_ROWS * D_DIM + M_ROWS;
        if (base < osz)     out[base]     = vq_loss;
        if (base + 1 < osz) out[base + 1] = expf(-red[0]);
    }
}

extern "C" void kernel_launch(void* const* d_in, const int* in_sizes, int n_in,
                              void* d_out, int out_size) {
    const float* z_e = (const float*)d_in[0];   // (65536, 64) f32
    const float* cb  = (const float*)d_in[1];   // (4096, 64) f32
    const float* ema = (const float*)d_in[2];   // (4096,) f32
    float* out = (float*)d_out;

    cudaFuncSetAttribute(vq_mma_kernel,
                         cudaFuncAttributeMaxDynamicSharedMemorySize, SMEM_DYN);

    vq_prep_c<<<K_CODES / 8, 256>>>(cb);
    vq_prep_A<<<M_ROWS / 8, 256>>>(z_e);
    vq_prep_B<<<K_CODES / 8, 256>>>(cb);
    vq_mma_kernel<<<MTILES, 256, SMEM_DYN>>>(out, z_e, cb, out_size);
    vq_finalize_kernel<<<1, 1024>>>(ema, out, out_size);
}

// round 5
// speedup vs baseline: 3.9980x; 1.0732x over previous
#include <cuda_runtime.h>
#include <cuda_bf16.h>
#include <math.h>

#define M_ROWS   65536
#define D_DIM    64
#define K_CODES  4096
#define KS       216                      // padded K stride (bf16 elems), 208 used
#define MT       128                      // rows per CTA
#define NT       128                      // codes per chunk
#define NCH      (K_CODES / NT)           // 32
#define MTILES   (M_ROWS / MT)            // 512
#define TILE_BYTES (MT * KS * 2)          // 55296 (A tile == B chunk size)
#define CP_UNITS   (TILE_BYTES / 16)      // 3456
#define SMEM_DYN   (3 * TILE_BYTES)       // A + 2x B

// ---- global scratch (static __device__; no runtime allocs) ----
__device__ __align__(16) unsigned char g_A[(size_t)M_ROWS * KS * 2];   // ~28 MB
__device__ __align__(16) unsigned char g_B[(size_t)K_CODES * KS * 2];  // ~1.8 MB
__device__ float g_c[K_CODES];                                         // 0.5*||e||^2
__device__ float g_partials[MTILES];

// ======================= helpers (compute_103-safe) =======================
__device__ __forceinline__ unsigned smem_u32(const void* p) {
    unsigned a;
    asm("{ .reg .u64 t; cvta.to.shared.u64 t, %1; cvt.u32.u64 %0, t; }" : "=r"(a) : "l"(p));
    return a;
}
__device__ __forceinline__ unsigned pack_bf16x2(float lo, float hi) {
    unsigned r;
    asm("cvt.rn.bf16x2.f32 %0, %1, %2;" : "=r"(r) : "f"(hi), "f"(lo));
    return r;  // low 16 bits (first in memory) = lo
}
__device__ __forceinline__ void cp_async16(unsigned saddr, const void* gaddr) {
    asm volatile("cp.async.cg.shared.global [%0], [%1], 16;" :: "r"(saddr), "l"(gaddr) : "memory");
}
__device__ __forceinline__ void cp_commit() {
    asm volatile("cp.async.commit_group;" ::: "memory");
}
template <int N>
__device__ __forceinline__ void cp_wait() {
    asm volatile("cp.async.wait_group %0;" :: "n"(N) : "memory");
}
__device__ __forceinline__ void ldsm_x4(unsigned* r, unsigned addr) {
    asm volatile("ldmatrix.sync.aligned.m8n8.x4.shared.b16 {%0,%1,%2,%3}, [%4];"
                 : "=r"(r[0]), "=r"(r[1]), "=r"(r[2]), "=r"(r[3]) : "r"(addr));
}
__device__ __forceinline__ void mma16816(float* c, const unsigned* a, const unsigned* b) {
    asm volatile(
        "mma.sync.aligned.m16n8k16.row.col.f32.bf16.bf16.f32 "
        "{%0,%1,%2,%3}, {%4,%5,%6,%7}, {%8,%9}, {%0,%1,%2,%3};"
        : "+f"(c[0]), "+f"(c[1]), "+f"(c[2]), "+f"(c[3])
        : "r"(a[0]), "r"(a[1]), "r"(a[2]), "r"(a[3]), "r"(b[0]), "r"(b[1]));
}
__device__ __forceinline__ void upd2(float& b, float& s, int& bi, int& si, float v, int c) {
    bool g1 = v > b;
    bool g2 = v > s;
    s  = g1 ? b  : (g2 ? v : s);
    si = g1 ? bi : (g2 ? c : si);
    b  = g1 ? v : b;
    bi = g1 ? c : bi;
}
// in-register merge of two top-2 sets (tie -> smaller index)
__device__ __forceinline__ void mergeL(float& best, float& sec, int& bi, int& si,
                                       float ob, float os, int oi, int osi) {
    bool take = (ob > best) || (ob == best && oi < bi);
    float nb  = take ? ob : best;  int nbi = take ? oi : bi;
    float c1  = take ? best : ob;  int c1i = take ? bi : oi;
    float c2  = take ? os : sec;   int c2i = take ? osi : si;
    bool t2   = (c2 > c1) || (c2 == c1 && c2i < c1i);
    sec  = t2 ? c2 : c1;  si = t2 ? c2i : c1i;
    best = nb;            bi = nbi;
}
// merge across lanes via shfl.bfly (tie -> smaller index)
__device__ __forceinline__ void merge2(float& best, float& sec, int& bi, int& si, int off) {
    float ob  = __shfl_xor_sync(0xffffffffu, best, off);
    int   oi  = __shfl_xor_sync(0xffffffffu, bi,   off);
    float os  = __shfl_xor_sync(0xffffffffu, sec,  off);
    int   osi = __shfl_xor_sync(0xffffffffu, si,   off);
    mergeL(best, sec, bi, si, ob, os, oi, osi);
}

// ===================== prep kernels =====================
__global__ void vq_prep_c(const float* __restrict__ cb) {
    int k    = blockIdx.x * 8 + (threadIdx.x >> 5);
    int lane = threadIdx.x & 31;
    float2 v = reinterpret_cast<const float2*>(cb + (size_t)k * D_DIM)[lane];
    float s  = v.x * v.x + v.y * v.y;
    #pragma unroll
    for (int o = 16; o > 0; o >>= 1) s += __shfl_down_sync(0xffffffffu, s, o);
    if (lane == 0) g_c[k] = 0.5f * s;
}

// A row m: [z_hi(0:64) | z_lo(64:128) | z_hi(128:192) | 1,1 @192,193 | 0 pad]
__global__ void vq_prep_A(const float* __restrict__ z) {
    int m = blockIdx.x * 8 + (threadIdx.x >> 5);
    int l = threadIdx.x & 31;
    float2 x = reinterpret_cast<const float2*>(z + (size_t)m * D_DIM)[l];
    float hx = __bfloat162float(__float2bfloat16(x.x));
    float hy = __bfloat162float(__float2bfloat16(x.y));
    unsigned H = pack_bf16x2(x.x, x.y);
    unsigned L = pack_bf16x2(x.x - hx, x.y - hy);
    unsigned* row = reinterpret_cast<unsigned*>(g_A) + (size_t)m * (KS / 2);
    row[l] = H; row[32 + l] = L; row[64 + l] = H;
    if (l == 0) row[96] = pack_bf16x2(1.0f, 1.0f);
    if (l >= 1 && l <= 11) row[96 + l] = 0u;
}

// B row k: [e_hi | e_hi | e_lo | -c_hi,-c_lo @192,193 | 0 pad]
__global__ void vq_prep_B(const float* __restrict__ cb) {
    int k = blockIdx.x * 8 + (threadIdx.x >> 5);
    int l = threadIdx.x & 31;
    float2 x = reinterpret_cast<const float2*>(cb + (size_t)k * D_DIM)[l];
    float hx = __bfloat162float(__float2bfloat16(x.x));
    float hy = __bfloat162float(__float2bfloat16(x.y));
    unsigned H = pack_bf16x2(x.x, x.y);
    unsigned L = pack_bf16x2(x.x - hx, x.y - hy);
    unsigned* row = reinterpret_cast<unsigned*>(g_B) + (size_t)k * (KS / 2);
    row[l] = H; row[32 + l] = H; row[64 + l] = L;
    if (l == 0) {
        float c  = g_c[k];
        float ch = __bfloat162float(__float2bfloat16(c));
        row[96] = pack_bf16x2(-ch, -(c - ch));
    }
    if (l >= 1 && l <= 11) row[96 + l] = 0u;
}

// ===================== main fused HMMA GEMM + argmax =====================
__global__ void __launch_bounds__(256, 1)
vq_mma_kernel(float* __restrict__ out, const float* __restrict__ z_e,
              const float* __restrict__ cb, int out_size_i) {
    extern __shared__ unsigned char smem_raw[];
    __shared__ float shred[8];

    const unsigned uA  = smem_u32(smem_raw);
    const unsigned uB0 = uA + TILE_BYTES;
    const unsigned uB1 = uB0 + TILE_BYTES;

    const int tid  = threadIdx.x;
    const int w    = tid >> 5;
    const int l    = tid & 31;
    const int wr   = w >> 1;          // row group 0..3 (rows wr*32..+31)
    const int wc   = w & 1;           // col group 0..1 (cols wc*64..+63)
    const int tile = blockIdx.x;

    // ---- prologue: A tile + B chunk 0 ----
    {
        const unsigned char* gA = g_A + (size_t)tile * TILE_BYTES;
        for (int u = tid; u < CP_UNITS; u += 256) cp_async16(uA + u * 16, gA + u * 16);
        for (int u = tid; u < CP_UNITS; u += 256) cp_async16(uB0 + u * 16, g_B + u * 16);
        cp_commit();
    }

    // ldmatrix lane offsets
    const unsigned aoff  = ((unsigned)(wr * 32 + (l & 7) + ((l >> 3) & 1) * 8) * KS
                            + (unsigned)(l >> 4) * 8) * 2;
    const unsigned A16   = 16u * KS * 2;     // +16 rows
    const unsigned boffB = ((unsigned)(wc * 64 + (l >> 4) * 8 + (l & 7)) * KS
                            + (unsigned)((l >> 3) & 1) * 8) * 2;
    const unsigned B16   = 16u * KS * 2;     // +16 codes

    float acc[64];
    #pragma unroll
    for (int i = 0; i < 64; i++) acc[i] = 0.0f;

    // 8 independent top-2 chains: [ra(2)][row-half(2)][parity(2)]
    float cb_[8], cs_[8];
    int   ci_[8], cj_[8];
    #pragma unroll
    for (int i = 0; i < 8; i++) {
        cb_[i] = -3.402823466e38f; cs_[i] = -3.402823466e38f;
        ci_[i] = 0; cj_[i] = 0;
    }

    for (int ch = 0; ch < NCH; ch++) {
        const unsigned ub = (ch & 1) ? uB1 : uB0;
        if (ch + 1 < NCH) {
            const unsigned ubn = (ch & 1) ? uB0 : uB1;
            const unsigned char* gBn = g_B + (size_t)(ch + 1) * TILE_BYTES;
            for (int u = tid; u < CP_UNITS; u += 256) cp_async16(ubn + u * 16, gBn + u * 16);
            cp_commit();
            cp_wait<1>();
        } else {
            cp_wait<0>();
        }
        __syncthreads();

        #pragma unroll
        for (int s = 0; s < 13; s++) {
            unsigned a0[4], a1[4];
            ldsm_x4(a0, uA + aoff + s * 32);
            ldsm_x4(a1, uA + aoff + A16 + s * 32);
            #pragma unroll
            for (int p = 0; p < 4; p++) {
                unsigned b[4];
                ldsm_x4(b, ub + boffB + (unsigned)p * B16 + s * 32);
                mma16816(&acc[((0 * 4 + p) * 2 + 0) * 4], a0, b);
                mma16816(&acc[((0 * 4 + p) * 2 + 1) * 4], a0, b + 2);
                mma16816(&acc[((1 * 4 + p) * 2 + 0) * 4], a1, b);
                mma16816(&acc[((1 * 4 + p) * 2 + 1) * 4], a1, b + 2);
            }
        }

        // ---- fold: 8 independent chains, depth 8 each ----
        const int colb = ch * NT + wc * 64 + 2 * (l & 3);
        #pragma unroll
        for (int ra = 0; ra < 2; ra++) {
            #pragma unroll
            for (int p = 0; p < 4; p++) {
                #pragma unroll
                for (int h = 0; h < 2; h++) {
                    const int q  = ((ra * 4 + p) * 2 + h) * 4;
                    const int c0 = colb + p * 16 + h * 8;
                    const int k0 = ra * 4 + 0 * 2 + (p & 1);   // row-half 0 chain
                    const int k1 = ra * 4 + 1 * 2 + (p & 1);   // row-half 1 chain
                    upd2(cb_[k0], cs_[k0], ci_[k0], cj_[k0], acc[q + 0], c0);
                    upd2(cb_[k0], cs_[k0], ci_[k0], cj_[k0], acc[q + 1], c0 + 1);
                    upd2(cb_[k1], cs_[k1], ci_[k1], cj_[k1], acc[q + 2], c0);
                    upd2(cb_[k1], cs_[k1], ci_[k1], cj_[k1], acc[q + 3], c0 + 1);
                    acc[q + 0] = 0.0f; acc[q + 1] = 0.0f;
                    acc[q + 2] = 0.0f; acc[q + 3] = 0.0f;
                }
            }
        }
        __syncthreads();
    }

    // ---- merge parity chains, then quad lanes ----
    float rb[4], rs[4]; int ri[4], rj[4];
    #pragma unroll
    for (int g = 0; g < 4; g++) {           // g = ra*2 + row-half
        rb[g] = cb_[g * 2]; rs[g] = cs_[g * 2]; ri[g] = ci_[g * 2]; rj[g] = cj_[g * 2];
        mergeL(rb[g], rs[g], ri[g], rj[g], cb_[g * 2 + 1], cs_[g * 2 + 1],
               ci_[g * 2 + 1], cj_[g * 2 + 1]);
        merge2(rb[g], rs[g], ri[g], rj[g], 1);
        merge2(rb[g], rs[g], ri[g], rj[g], 2);
    }

    // per (wc, row) results -> smem (alias A region; safe after final sync)
    float* s_b  = reinterpret_cast<float*>(smem_raw);          // [2][128]
    float* s_s  = s_b + 256;
    int*   s_bi = reinterpret_cast<int*>(s_s + 256);
    int*   s_si = s_bi + 256;
    if ((l & 3) == 0) {
        #pragma unroll
        for (int g = 0; g < 4; g++) {
            const int ra = g >> 1, rh = g & 1;
            const int row = wr * 32 + ra * 16 + rh * 8 + (l >> 2);
            s_b[wc * 128 + row]  = rb[g];
            s_s[wc * 128 + row]  = rs[g];
            s_bi[wc * 128 + row] = ri[g];
            s_si[wc * 128 + row] = rj[g];
        }
    }
    __syncthreads();

    // ---- merge col-groups, exact fp32 rescore of top-2, outputs, loss ----
    const size_t osz = (size_t)out_size_i;
    float lsum = 0.0f;
    if (tid < 128) {
        float b1 = s_b[tid],        ss1 = s_s[tid];
        int   i1 = s_bi[tid],       j1  = s_si[tid];
        mergeL(b1, ss1, i1, j1, s_b[128 + tid], s_s[128 + tid],
               s_bi[128 + tid], s_si[128 + tid]);
        const int bidx = i1, sidx = j1;

        const int m = tile * MT + tid;
        const float4* zr = reinterpret_cast<const float4*>(z_e + (size_t)m * D_DIM);
        const float4* eb = reinterpret_cast<const float4*>(cb + (size_t)bidx * D_DIM);
        const float4* es = reinterpret_cast<const float4*>(cb + (size_t)sidx * D_DIM);
        float sb = -g_c[bidx], ss = -g_c[sidx];
        #pragma unroll
        for (int j = 0; j < 16; j++) {
            float4 zz = zr[j], b = eb[j], s2 = es[j];
            sb += zz.x * b.x + zz.y * b.y + zz.z * b.z + zz.w * b.w;
            ss += zz.x * s2.x + zz.y * s2.y + zz.z * s2.z + zz.w * s2.w;
        }
        const int fin = (ss > sb || (ss == sb && sidx < bidx)) ? sidx : bidx;

        const size_t MD    = (size_t)M_ROWS * D_DIM;
        const size_t base2 = MD + M_ROWS + 2;
        const float4* er = reinterpret_cast<const float4*>(cb + (size_t)fin * D_DIM);
        float4* out4 = reinterpret_cast<float4*>(out);
        float2* out2 = reinterpret_cast<float2*>(out);
        const size_t o1 = (size_t)m * D_DIM;
        const size_t o3 = base2 + (size_t)m * D_DIM;

        #pragma unroll
        for (int j = 0; j < 16; j++) {
            float4 e = er[j];
            float4 z = zr[j];
            float4 zst;
            zst.x = z.x + (e.x - z.x);
            zst.y = z.y + (e.y - z.y);
            zst.z = z.z + (e.z - z.z);
            zst.w = z.w + (e.w - z.w);
            float d0 = z.x - e.x, d1 = z.y - e.y, d2 = z.z - e.z, d3 = z.w - e.w;
            lsum += d0 * d0 + d1 * d1 + d2 * d2 + d3 * d3;
            if (o1 + (size_t)j * 4 + 4 <= osz) out4[o1 / 4 + j] = zst;
            if (o3 + (size_t)j * 4 + 4 <= osz) {
                out2[o3 / 2 + 2 * j]     = make_float2(e.x, e.y);
                out2[o3 / 2 + 2 * j + 1] = make_float2(e.z, e.w);
            }
        }
        if (MD + (size_t)m < osz) out[MD + (size_t)m] = (float)fin;
    }

    #pragma unroll
    for (int o = 16; o > 0; o >>= 1) lsum += __shfl_down_sync(0xffffffffu, lsum, o);
    if ((tid & 31) == 0) shred[w] = lsum;
    __syncthreads();
    if (tid == 0) {
        float t = 0.0f;
        #pragma unroll
        for (int i = 0; i < 8; i++) t += shred[i];
        g_partials[tile] = t;
    }
}

// ===================== finalize: vq_loss + perplexity =====================
__global__ void vq_finalize_kernel(const float* __restrict__ ema,
                                   float* __restrict__ out, int out_size_i) {
    __shared__ float red[1024];
    const size_t osz = (size_t)out_size_i;
    const int tid = threadIdx.x;

    float v = (tid < MTILES) ? g_partials[tid] : 0.0f;
    red[tid] = v;
    for (int o = 512; o > 0; o >>= 1) {
        __syncthreads();
        if (tid < o) red[tid] += red[tid + o];
    }
    __syncthreads();
    const float vq_loss = 0.25f * red[0] / (float)((size_t)M_ROWS * D_DIM);
    __syncthreads();

    float s = 0.0f;
    for (int i = tid; i < K_CODES; i += 1024) s += ema[i] + 1e-10f;
    red[tid] = s;
    for (int o = 512; o > 0; o >>= 1) {
        __syncthreads();
        if (tid < o) red[tid] += red[tid + o];
    }
    __syncthreads();
    const float S = red[0];
    __syncthreads();

    float ent = 0.0f;
    for (int i = tid; i < K_CODES; i += 1024) {
        float p = (ema[i] + 1e-10f) / S;
        ent += p * logf(p);
    }
    red[tid] = ent;
    for (int o = 512; o > 0; o >>= 1) {
        __syncthreads();
        if (tid < o) red[tid] += red[tid + o];
    }
    __syncthreads();

    if (tid == 0) {
        const size_t base = (size_t)M_ROWS * D_DIM + M_ROWS;
        if (base < osz)     out[base]     = vq_loss;
        if (base + 1 < osz) out[base + 1] = expf(-red[0]);
    }
}

extern "C" void kernel_launch(void* const* d_in, const int* in_sizes, int n_in,
                              void* d_out, int out_size) {
    const float* z_e = (const float*)d_in[0];   // (65536, 64) f32
    const float* cb  = (const float*)d_in[1];   // (4096, 64) f32
    const float* ema = (const float*)d_in[2];   // (4096,) f32
    float* out = (float*)d_out;

    cudaFuncSetAttribute(vq_mma_kernel,
                         cudaFuncAttributeMaxDynamicSharedMemorySize, SMEM_DYN);

    vq_prep_c<<<K_CODES / 8, 256>>>(cb);
    vq_prep_A<<<M_ROWS / 8, 256>>>(z_e);
    vq_prep_B<<<K_CODES / 8, 256>>>(cb);
    vq_mma_kernel<<<MTILES, 256, SMEM_DYN>>>(out, z_e, cb, out_size);
    vq_finalize_kernel<<<1, 1024>>>(ema, out, out_size);
}

// round 6
// speedup vs baseline: 8.6759x; 2.1701x over previous
#include <cuda_runtime.h>
#include <cuda_bf16.h>
#include <math.h>

#define M_ROWS   65536
#define D_DIM    64
#define K_CODES  4096
#define KS       88                       // padded K stride (bf16), 80 used
#define NSTEP    5                        // k16 steps (5*16 = 80)
#define MT       128                      // rows per CTA
#define NT       128                      // codes per chunk
#define NCH      (K_CODES / NT)           // 32
#define MTILES   (M_ROWS / MT)            // 512
#define TILE_BYTES (MT * KS * 2)          // 22528
#define CP_UNITS   (TILE_BYTES / 16)      // 1408
#define SMEM_DYN   (3 * TILE_BYTES)       // 67584: A + 2x B

// ---- global scratch (static __device__; no runtime allocs) ----
__device__ __align__(16) unsigned char g_A[(size_t)M_ROWS * KS * 2];   // ~11.5 MB
__device__ __align__(16) unsigned char g_B[(size_t)K_CODES * KS * 2];  // ~0.7 MB
__device__ float g_c[K_CODES];                                         // 0.5*||e||^2
__device__ float g_partials[MTILES];

#define NEG_INF (-3.402823466e38f)

// ======================= helpers (compute_103-safe) =======================
__device__ __forceinline__ unsigned smem_u32(const void* p) {
    unsigned a;
    asm("{ .reg .u64 t; cvta.to.shared.u64 t, %1; cvt.u32.u64 %0, t; }" : "=r"(a) : "l"(p));
    return a;
}
__device__ __forceinline__ unsigned pack_bf16x2(float lo, float hi) {
    unsigned r;
    asm("cvt.rn.bf16x2.f32 %0, %1, %2;" : "=r"(r) : "f"(hi), "f"(lo));
    return r;  // low 16 bits (first in memory) = lo
}
__device__ __forceinline__ void cp_async16(unsigned saddr, const void* gaddr) {
    asm volatile("cp.async.cg.shared.global [%0], [%1], 16;" :: "r"(saddr), "l"(gaddr) : "memory");
}
__device__ __forceinline__ void cp_commit() {
    asm volatile("cp.async.commit_group;" ::: "memory");
}
template <int N>
__device__ __forceinline__ void cp_wait() {
    asm volatile("cp.async.wait_group %0;" :: "n"(N) : "memory");
}
__device__ __forceinline__ void ldsm_x4(unsigned* r, unsigned addr) {
    asm volatile("ldmatrix.sync.aligned.m8n8.x4.shared.b16 {%0,%1,%2,%3}, [%4];"
                 : "=r"(r[0]), "=r"(r[1]), "=r"(r[2]), "=r"(r[3]) : "r"(addr));
}
__device__ __forceinline__ void mma16816(float* c, const unsigned* a, const unsigned* b) {
    asm volatile(
        "mma.sync.aligned.m16n8k16.row.col.f32.bf16.bf16.f32 "
        "{%0,%1,%2,%3}, {%4,%5,%6,%7}, {%8,%9}, {%0,%1,%2,%3};"
        : "+f"(c[0]), "+f"(c[1]), "+f"(c[2]), "+f"(c[3])
        : "r"(a[0]), "r"(a[1]), "r"(a[2]), "r"(a[3]), "r"(b[0]), "r"(b[1]));
}
// first k-step: c-input = 0 (avoids per-chunk accumulator zeroing)
__device__ __forceinline__ void mma16816_z(float* c, const unsigned* a, const unsigned* b) {
    asm volatile(
        "mma.sync.aligned.m16n8k16.row.col.f32.bf16.bf16.f32 "
        "{%0,%1,%2,%3}, {%4,%5,%6,%7}, {%8,%9}, {%10,%10,%10,%10};"
        : "=f"(c[0]), "=f"(c[1]), "=f"(c[2]), "=f"(c[3])
        : "r"(a[0]), "r"(a[1]), "r"(a[2]), "r"(a[3]), "r"(b[0]), "r"(b[1]), "f"(0.0f));
}
__device__ __forceinline__ void upd2(float& b, float& s, int& bi, int& si, float v, int c) {
    bool g1 = v > b;
    bool g2 = v > s;
    s  = g1 ? b  : (g2 ? v : s);
    si = g1 ? bi : (g2 ? c : si);
    b  = g1 ? v : b;
    bi = g1 ? c : bi;
}
// ordered insert into sorted-desc top-3 (tie -> smaller index)
__device__ __forceinline__ void ins3(float* v, int* ix, float nv, int ni) {
    bool b0 = (nv > v[0]) || (nv == v[0] && ni < ix[0]);
    bool b1 = (nv > v[1]) || (nv == v[1] && ni < ix[1]);
    bool b2 = (nv > v[2]) || (nv == v[2] && ni < ix[2]);
    if (b0) { v[2]=v[1]; ix[2]=ix[1]; v[1]=v[0]; ix[1]=ix[0]; v[0]=nv; ix[0]=ni; }
    else if (b1) { v[2]=v[1]; ix[2]=ix[1]; v[1]=nv; ix[1]=ni; }
    else if (b2) { v[2]=nv; ix[2]=ni; }
}
// merge partner lane's top-3 via shfl.bfly
__device__ __forceinline__ void merge3_shfl(float* v, int* ix, int off) {
    float ov[3]; int oi[3];
    #pragma unroll
    for (int j = 0; j < 3; j++) {
        ov[j] = __shfl_xor_sync(0xffffffffu, v[j], off);
        oi[j] = __shfl_xor_sync(0xffffffffu, ix[j], off);
    }
    #pragma unroll
    for (int j = 0; j < 3; j++) ins3(v, ix, ov[j], oi[j]);
}

// ===================== prep kernels =====================
__global__ void vq_prep_c(const float* __restrict__ cb) {
    int k    = blockIdx.x * 8 + (threadIdx.x >> 5);
    int lane = threadIdx.x & 31;
    float2 v = reinterpret_cast<const float2*>(cb + (size_t)k * D_DIM)[lane];
    float s  = v.x * v.x + v.y * v.y;
    #pragma unroll
    for (int o = 16; o > 0; o >>= 1) s += __shfl_down_sync(0xffffffffu, s, o);
    if (lane == 0) g_c[k] = 0.5f * s;
}

// A row m: [zh(0:64) | 1,1 @64,65 | 0 pad to 88]
__global__ void vq_prep_A(const float* __restrict__ z) {
    int m = blockIdx.x * 8 + (threadIdx.x >> 5);
    int l = threadIdx.x & 31;
    float2 x = reinterpret_cast<const float2*>(z + (size_t)m * D_DIM)[l];
    unsigned H = pack_bf16x2(x.x, x.y);
    unsigned* row = reinterpret_cast<unsigned*>(g_A) + (size_t)m * (KS / 2);
    row[l] = H;
    if (l == 0) row[32] = pack_bf16x2(1.0f, 1.0f);
    if (l >= 1 && l <= 11) row[32 + l] = 0u;
}

// B row k: [eh(0:64) | -c_hi,-c_lo @64,65 | 0 pad to 88]
__global__ void vq_prep_B(const float* __restrict__ cb) {
    int k = blockIdx.x * 8 + (threadIdx.x >> 5);
    int l = threadIdx.x & 31;
    float2 x = reinterpret_cast<const float2*>(cb + (size_t)k * D_DIM)[l];
    unsigned H = pack_bf16x2(x.x, x.y);
    unsigned* row = reinterpret_cast<unsigned*>(g_B) + (size_t)k * (KS / 2);
    row[l] = H;
    if (l == 0) {
        float c  = g_c[k];
        float ch = __bfloat162float(__float2bfloat16(c));
        row[32] = pack_bf16x2(-ch, -(c - ch));
    }
    if (l >= 1 && l <= 11) row[32 + l] = 0u;
}

// ===================== main fused HMMA GEMM + argmax =====================
__global__ void __launch_bounds__(256, 2)
vq_mma_kernel(float* __restrict__ out, const float* __restrict__ z_e,
              const float* __restrict__ cb, int out_size_i) {
    extern __shared__ unsigned char smem_raw[];
    __shared__ float shred[8];

    const unsigned uA  = smem_u32(smem_raw);
    const unsigned uB0 = uA + TILE_BYTES;
    const unsigned uB1 = uB0 + TILE_BYTES;

    const int tid  = threadIdx.x;
    const int w    = tid >> 5;
    const int l    = tid & 31;
    const int wr   = w >> 1;          // row group 0..3 (rows wr*32..+31)
    const int wc   = w & 1;           // col group 0..1 (cols wc*64..+63)
    const int tile = blockIdx.x;

    // ---- prologue: A tile + B chunk 0 ----
    {
        const unsigned char* gA = g_A + (size_t)tile * TILE_BYTES;
        for (int u = tid; u < CP_UNITS; u += 256) cp_async16(uA + u * 16, gA + u * 16);
        for (int u = tid; u < CP_UNITS; u += 256) cp_async16(uB0 + u * 16, g_B + u * 16);
        cp_commit();
    }

    // ldmatrix lane offsets
    const unsigned aoff  = ((unsigned)(wr * 32 + (l & 7) + ((l >> 3) & 1) * 8) * KS
                            + (unsigned)(l >> 4) * 8) * 2;
    const unsigned A16   = 16u * KS * 2;     // +16 rows
    const unsigned boffB = ((unsigned)(wc * 64 + (l >> 4) * 8 + (l & 7)) * KS
                            + (unsigned)((l >> 3) & 1) * 8) * 2;
    const unsigned B16   = 16u * KS * 2;     // +16 codes

    float acc[64];

    // 4 top-2 chains over PAIR-maxes, one per row this lane covers:
    // g = ra*2 + rowhalf, row = wr*32 + ra*16 + rowhalf*8 + (l>>2)
    float cb_[4], cs_[4];
    int   ci_[4], cj_[4];
    #pragma unroll
    for (int i = 0; i < 4; i++) {
        cb_[i] = NEG_INF; cs_[i] = NEG_INF; ci_[i] = 0; cj_[i] = 0;
    }

    for (int ch = 0; ch < NCH; ch++) {
        const unsigned ub = (ch & 1) ? uB1 : uB0;
        if (ch + 1 < NCH) {
            const unsigned ubn = (ch & 1) ? uB0 : uB1;
            const unsigned char* gBn = g_B + (size_t)(ch + 1) * TILE_BYTES;
            for (int u = tid; u < CP_UNITS; u += 256) cp_async16(ubn + u * 16, gBn + u * 16);
            cp_commit();
            cp_wait<1>();
        } else {
            cp_wait<0>();
        }
        __syncthreads();

        #pragma unroll
        for (int s = 0; s < NSTEP; s++) {
            unsigned a0[4], a1[4];
            ldsm_x4(a0, uA + aoff + s * 32);
            ldsm_x4(a1, uA + aoff + A16 + s * 32);
            #pragma unroll
            for (int p = 0; p < 4; p++) {
                unsigned b[4];
                ldsm_x4(b, ub + boffB + (unsigned)p * B16 + s * 32);
                if (s == 0) {
                    mma16816_z(&acc[((0 * 4 + p) * 2 + 0) * 4], a0, b);
                    mma16816_z(&acc[((0 * 4 + p) * 2 + 1) * 4], a0, b + 2);
                    mma16816_z(&acc[((1 * 4 + p) * 2 + 0) * 4], a1, b);
                    mma16816_z(&acc[((1 * 4 + p) * 2 + 1) * 4], a1, b + 2);
                } else {
                    mma16816(&acc[((0 * 4 + p) * 2 + 0) * 4], a0, b);
                    mma16816(&acc[((0 * 4 + p) * 2 + 1) * 4], a0, b + 2);
                    mma16816(&acc[((1 * 4 + p) * 2 + 0) * 4], a1, b);
                    mma16816(&acc[((1 * 4 + p) * 2 + 1) * 4], a1, b + 2);
                }
            }
        }

        // ---- fold: pair-max (2 adjacent cols) -> per-row top-2 chains ----
        const int colb = ch * NT + wc * 64 + 2 * (l & 3);
        #pragma unroll
        for (int ra = 0; ra < 2; ra++) {
            #pragma unroll
            for (int p = 0; p < 4; p++) {
                #pragma unroll
                for (int h = 0; h < 2; h++) {
                    const int q  = ((ra * 4 + p) * 2 + h) * 4;
                    const int c0 = colb + p * 16 + h * 8;
                    float pm0 = fmaxf(acc[q + 0], acc[q + 1]);   // row-half 0
                    float pm1 = fmaxf(acc[q + 2], acc[q + 3]);   // row-half 1
                    upd2(cb_[ra * 2 + 0], cs_[ra * 2 + 0], ci_[ra * 2 + 0], cj_[ra * 2 + 0], pm0, c0);
                    upd2(cb_[ra * 2 + 1], cs_[ra * 2 + 1], ci_[ra * 2 + 1], cj_[ra * 2 + 1], pm1, c0);
                }
            }
        }
        __syncthreads();   // all reads of this buffer done before next prefetch overwrites
    }

    // ---- per-row top-3 pairs: promote chain top-2 to top-3, quad-merge ----
    // smem result arrays (alias A region; safe after the final sync above)
    float* s_v0 = reinterpret_cast<float*>(smem_raw);            // [2][128]
    float* s_v1 = s_v0 + 256;
    float* s_v2 = s_v1 + 256;
    int*   s_i0 = reinterpret_cast<int*>(s_v2 + 256);
    int*   s_i1 = s_i0 + 256;
    int*   s_i2 = s_i1 + 256;

    #pragma unroll
    for (int g = 0; g < 4; g++) {
        float tv[3]; int ti[3];
        tv[0] = cb_[g]; ti[0] = ci_[g];
        tv[1] = cs_[g]; ti[1] = cj_[g];
        tv[2] = NEG_INF; ti[2] = 0;
        merge3_shfl(tv, ti, 1);
        merge3_shfl(tv, ti, 2);
        if ((l & 3) == 0) {
            const int ra = g >> 1, rh = g & 1;
            const int row = wr * 32 + ra * 16 + rh * 8 + (l >> 2);
            const int ix  = wc * 128 + row;
            s_v0[ix] = tv[0]; s_v1[ix] = tv[1]; s_v2[ix] = tv[2];
            s_i0[ix] = ti[0]; s_i1[ix] = ti[1]; s_i2[ix] = ti[2];
        }
    }
    __syncthreads();

    // ---- merge col-groups, exact fp32 rescore of top-3 pairs (6 codes) ----
    const size_t osz = (size_t)out_size_i;
    float lsum = 0.0f;
    if (tid < 128) {
        float tv[3]; int ti[3];
        tv[0] = s_v0[tid]; ti[0] = s_i0[tid];
        tv[1] = s_v1[tid]; ti[1] = s_i1[tid];
        tv[2] = s_v2[tid]; ti[2] = s_i2[tid];
        ins3(tv, ti, s_v0[128 + tid], s_i0[128 + tid]);
        ins3(tv, ti, s_v1[128 + tid], s_i1[128 + tid]);
        ins3(tv, ti, s_v2[128 + tid], s_i2[128 + tid]);

        const int m = tile * MT + tid;
        const float4* zr = reinterpret_cast<const float4*>(z_e + (size_t)m * D_DIM);
        float4 zv[16];
        #pragma unroll
        for (int j = 0; j < 16; j++) zv[j] = zr[j];

        float bestv = NEG_INF;
        int   fin   = K_CODES;
        #pragma unroll
        for (int cand = 0; cand < 6; cand++) {
            const int code = ti[cand >> 1] + (cand & 1);
            const float4* er = reinterpret_cast<const float4*>(cb + (size_t)code * D_DIM);
            float s = -g_c[code];
            #pragma unroll
            for (int j = 0; j < 16; j++) {
                float4 e = er[j];
                s += zv[j].x * e.x + zv[j].y * e.y + zv[j].z * e.z + zv[j].w * e.w;
            }
            if (s > bestv || (s == bestv && code < fin)) { bestv = s; fin = code; }
        }

        // ---- outputs ----
        const size_t MD    = (size_t)M_ROWS * D_DIM;
        const size_t base2 = MD + M_ROWS + 2;
        const float4* er = reinterpret_cast<const float4*>(cb + (size_t)fin * D_DIM);
        float4* out4 = reinterpret_cast<float4*>(out);
        float2* out2 = reinterpret_cast<float2*>(out);
        const size_t o1 = (size_t)m * D_DIM;
        const size_t o3 = base2 + (size_t)m * D_DIM;

        #pragma unroll
        for (int j = 0; j < 16; j++) {
            float4 e = er[j];
            float4 z = zv[j];
            float4 zst;
            zst.x = z.x + (e.x - z.x);
            zst.y = z.y + (e.y - z.y);
            zst.z = z.z + (e.z - z.z);
            zst.w = z.w + (e.w - z.w);
            float d0 = z.x - e.x, d1 = z.y - e.y, d2 = z.z - e.z, d3 = z.w - e.w;
            lsum += d0 * d0 + d1 * d1 + d2 * d2 + d3 * d3;
            if (o1 + (size_t)j * 4 + 4 <= osz) out4[o1 / 4 + j] = zst;
            if (o3 + (size_t)j * 4 + 4 <= osz) {
                out2[o3 / 2 + 2 * j]     = make_float2(e.x, e.y);
                out2[o3 / 2 + 2 * j + 1] = make_float2(e.z, e.w);
            }
        }
        if (MD + (size_t)m < osz) out[MD + (size_t)m] = (float)fin;
    }

    #pragma unroll
    for (int o = 16; o > 0; o >>= 1) lsum += __shfl_down_sync(0xffffffffu, lsum, o);
    if ((tid & 31) == 0) shred[w] = lsum;
    __syncthreads();
    if (tid == 0) {
        float t = 0.0f;
        #pragma unroll
        for (int i = 0; i < 8; i++) t += shred[i];
        g_partials[tile] = t;
    }
}

// ===================== finalize: vq_loss + perplexity =====================
__global__ void vq_finalize_kernel(const float* __restrict__ ema,
                                   float* __restrict__ out, int out_size_i) {
    __shared__ float red[1024];
    const size_t osz = (size_t)out_size_i;
    const int tid = threadIdx.x;

    float v = (tid < MTILES) ? g_partials[tid] : 0.0f;
    red[tid] = v;
    for (int o = 512; o > 0; o >>= 1) {
        __syncthreads();
        if (tid < o) red[tid] += red[tid + o];
    }
    __syncthreads();
    const float vq_loss = 0.25f * red[0] / (float)((size_t)M_ROWS * D_DIM);
    __syncthreads();

    float s = 0.0f;
    for (int i = tid; i < K_CODES; i += 1024) s += ema[i] + 1e-10f;
    red[tid] = s;
    for (int o = 512; o > 0; o >>= 1) {
        __syncthreads();
        if (tid < o) red[tid] += red[tid + o];
    }
    __syncthreads();
    const float S = red[0];
    __syncthreads();

    float ent = 0.0f;
    for (int i = tid; i < K_CODES; i += 1024) {
        float p = (ema[i] + 1e-10f) / S;
        ent += p * logf(p);
    }
    red[tid] = ent;
    for (int o = 512; o > 0; o >>= 1) {
        __syncthreads();
        if (tid < o) red[tid] += red[tid + o];
    }
    __syncthreads();

    if (tid == 0) {
        const size_t base = (size_t)M_ROWS * D_DIM + M_ROWS;
        if (base < osz)     out[base]     = vq_loss;
        if (base + 1 < osz) out[base + 1] = expf(-red[0]);
    }
}

extern "C" void kernel_launch(void* const* d_in, const int* in_sizes, int n_in,
                              void* d_out, int out_size) {
    const float* z_e = (const float*)d_in[0];   // (65536, 64) f32
    const float* cb  = (const float*)d_in[1];   // (4096, 64) f32
    const float* ema = (const float*)d_in[2];   // (4096,) f32
    float* out = (float*)d_out;

    cudaFuncSetAttribute(vq_mma_kernel,
                         cudaFuncAttributeMaxDynamicSharedMemorySize, SMEM_DYN);

    vq_prep_c<<<K_CODES / 8, 256>>>(cb);
    vq_prep_A<<<M_ROWS / 8, 256>>>(z_e);
    vq_prep_B<<<K_CODES / 8, 256>>>(cb);
    vq_mma_kernel<<<MTILES, 256, SMEM_DYN>>>(out, z_e, cb, out_size);
    vq_finalize_kernel<<<1, 1024>>>(ema, out, out_size);
}

// round 8
// speedup vs baseline: 8.7588x; 1.0096x over previous
#include <cuda_runtime.h>
#include <cuda_bf16.h>
#include <math.h>

#define M_ROWS   65536
#define D_DIM    64
#define K_CODES  4096
#define KS       88                       // padded K stride (bf16), 80 used
#define NSTEP    5                        // k16 steps (5*16 = 80)
#define MT       128                      // rows per CTA
#define NT       128                      // codes per chunk
#define NCH      (K_CODES / NT)           // 32
#define MTILES   (M_ROWS / MT)            // 512
#define TILE_BYTES (MT * KS * 2)          // 22528
#define CP_UNITS   (TILE_BYTES / 16)      // 1408
#define SMEM_DYN   (3 * TILE_BYTES)       // 67584: A + 2x B

// ---- global scratch (static __device__; no runtime allocs) ----
__device__ __align__(16) unsigned char g_A[(size_t)M_ROWS * KS * 2];   // ~11.5 MB
__device__ __align__(16) unsigned char g_B[(size_t)K_CODES * KS * 2];  // ~0.7 MB
__device__ float g_c[K_CODES];                                         // 0.5*||e||^2
__device__ float g_partials[MTILES];

#define NEG_INF (-3.402823466e38f)

// ======================= helpers (compute_103-safe) =======================
__device__ __forceinline__ unsigned smem_u32(const void* p) {
    unsigned a;
    asm("{ .reg .u64 t; cvta.to.shared.u64 t, %1; cvt.u32.u64 %0, t; }" : "=r"(a) : "l"(p));
    return a;
}
__device__ __forceinline__ unsigned pack_bf16x2(float lo, float hi) {
    unsigned r;
    asm("cvt.rn.bf16x2.f32 %0, %1, %2;" : "=r"(r) : "f"(hi), "f"(lo));
    return r;  // low 16 bits (first in memory) = lo
}
__device__ __forceinline__ void cp_async16(unsigned saddr, const void* gaddr) {
    asm volatile("cp.async.cg.shared.global [%0], [%1], 16;" :: "r"(saddr), "l"(gaddr) : "memory");
}
__device__ __forceinline__ void cp_commit() {
    asm volatile("cp.async.commit_group;" ::: "memory");
}
template <int N>
__device__ __forceinline__ void cp_wait() {
    asm volatile("cp.async.wait_group %0;" :: "n"(N) : "memory");
}
__device__ __forceinline__ void ldsm_x4(unsigned* r, unsigned addr) {
    asm volatile("ldmatrix.sync.aligned.m8n8.x4.shared.b16 {%0,%1,%2,%3}, [%4];"
                 : "=r"(r[0]), "=r"(r[1]), "=r"(r[2]), "=r"(r[3]) : "r"(addr));
}
__device__ __forceinline__ void mma16816(float* c, const unsigned* a, const unsigned* b) {
    asm volatile(
        "mma.sync.aligned.m16n8k16.row.col.f32.bf16.bf16.f32 "
        "{%0,%1,%2,%3}, {%4,%5,%6,%7}, {%8,%9}, {%0,%1,%2,%3};"
        : "+f"(c[0]), "+f"(c[1]), "+f"(c[2]), "+f"(c[3])
        : "r"(a[0]), "r"(a[1]), "r"(a[2]), "r"(a[3]), "r"(b[0]), "r"(b[1]));
}
// first k-step: c-input = 0 (avoids per-chunk accumulator zeroing)
__device__ __forceinline__ void mma16816_z(float* c, const unsigned* a, const unsigned* b) {
    asm volatile(
        "mma.sync.aligned.m16n8k16.row.col.f32.bf16.bf16.f32 "
        "{%0,%1,%2,%3}, {%4,%5,%6,%7}, {%8,%9}, {%10,%10,%10,%10};"
        : "=f"(c[0]), "=f"(c[1]), "=f"(c[2]), "=f"(c[3])
        : "r"(a[0]), "r"(a[1]), "r"(a[2]), "r"(a[3]), "r"(b[0]), "r"(b[1]), "f"(0.0f));
}
// ordered insert into sorted-desc top-3 of plain floats (values are bit-distinct)
__device__ __forceinline__ void ins3f(float* v, float nv) {
    if (nv > v[0])      { v[2] = v[1]; v[1] = v[0]; v[0] = nv; }
    else if (nv > v[1]) { v[2] = v[1]; v[1] = nv; }
    else if (nv > v[2]) { v[2] = nv; }
}
__device__ __forceinline__ void merge3f_shfl(float* v, int off) {
    float ov[3];
    #pragma unroll
    for (int j = 0; j < 3; j++) ov[j] = __shfl_xor_sync(0xffffffffu, v[j], off);
    #pragma unroll
    for (int j = 0; j < 3; j++) ins3f(v, ov[j]);
}

// ===================== prep kernels =====================
__global__ void vq_prep_c(const float* __restrict__ cb) {
    int k    = blockIdx.x * 8 + (threadIdx.x >> 5);
    int lane = threadIdx.x & 31;
    float2 v = reinterpret_cast<const float2*>(cb + (size_t)k * D_DIM)[lane];
    float s  = v.x * v.x + v.y * v.y;
    #pragma unroll
    for (int o = 16; o > 0; o >>= 1) s += __shfl_down_sync(0xffffffffu, s, o);
    if (lane == 0) g_c[k] = 0.5f * s;
}

// A row m: [zh(0:64) | 1,1 @64,65 | 0 pad to 88]
__global__ void vq_prep_A(const float* __restrict__ z) {
    int m = blockIdx.x * 8 + (threadIdx.x >> 5);
    int l = threadIdx.x & 31;
    float2 x = reinterpret_cast<const float2*>(z + (size_t)m * D_DIM)[l];
    unsigned H = pack_bf16x2(x.x, x.y);
    unsigned* row = reinterpret_cast<unsigned*>(g_A) + (size_t)m * (KS / 2);
    row[l] = H;
    if (l == 0) row[32] = pack_bf16x2(1.0f, 1.0f);
    if (l >= 1 && l <= 11) row[32 + l] = 0u;
}

// B row k: [eh(0:64) | -c_hi,-c_lo @64,65 | 0 pad to 88]
__global__ void vq_prep_B(const float* __restrict__ cb) {
    int k = blockIdx.x * 8 + (threadIdx.x >> 5);
    int l = threadIdx.x & 31;
    float2 x = reinterpret_cast<const float2*>(cb + (size_t)k * D_DIM)[l];
    unsigned H = pack_bf16x2(x.x, x.y);
    unsigned* row = reinterpret_cast<unsigned*>(g_B) + (size_t)k * (KS / 2);
    row[l] = H;
    if (l == 0) {
        float c  = g_c[k];
        float ch = __bfloat162float(__float2bfloat16(c));
        row[32] = pack_bf16x2(-ch, -(c - ch));
    }
    if (l >= 1 && l <= 11) row[32 + l] = 0u;
}

// ===================== main fused HMMA GEMM + argmax =====================
// acc layout: ACC(ra, cb, p)[0,1] = rowhalf 0 cols {0,1}; [2,3] = rowhalf 1
#define ACC(ra, cbk, p) (&acc[(((ra) * 2 + (cbk)) * 2 + (p)) * 4])

__global__ void __launch_bounds__(256, 2)
vq_mma_kernel(float* __restrict__ out, const float* __restrict__ z_e,
              const float* __restrict__ cb, int out_size_i) {
    extern __shared__ unsigned char smem_raw[];
    __shared__ float shred[8];

    const unsigned uA  = smem_u32(smem_raw);
    const unsigned uB0 = uA + TILE_BYTES;
    const unsigned uB1 = uB0 + TILE_BYTES;

    const int tid  = threadIdx.x;
    const int w    = tid >> 5;
    const int l    = tid & 31;
    const int wr   = w >> 1;          // row group 0..3 (rows wr*32..+31)
    const int wc   = w & 1;           // col group 0..1 (32 cols within each 64-col half)
    const int tile = blockIdx.x;

    // ---- prologue: A tile + B chunk 0, then B chunk 1 ----
    {
        const unsigned char* gA = g_A + (size_t)tile * TILE_BYTES;
        for (int u = tid; u < CP_UNITS; u += 256) cp_async16(uA + u * 16, gA + u * 16);
        for (int u = tid; u < CP_UNITS; u += 256) cp_async16(uB0 + u * 16, g_B + u * 16);
        cp_commit();
        const unsigned char* gB1 = g_B + (size_t)TILE_BYTES;
        for (int u = tid; u < CP_UNITS; u += 256) cp_async16(uB1 + u * 16, gB1 + u * 16);
        cp_commit();
    }
    cp_wait<1>();          // A + B0 landed
    __syncthreads();

    // ---- load A into registers once (rows wr*32..+31, all 80 k) ----
    const unsigned a_lane = ((unsigned)(wr * 32 + (l & 7) + ((l >> 3) & 1) * 8) * KS
                             + (unsigned)(l >> 4) * 8) * 2;
    unsigned aA[2][NSTEP][4];
    #pragma unroll
    for (int ra = 0; ra < 2; ra++)
        #pragma unroll
        for (int s = 0; s < NSTEP; s++)
            ldsm_x4(aA[ra][s], uA + a_lane + (unsigned)ra * (16u * KS * 2) + (unsigned)s * 32);

    // B ldsm lane offset (within a 16-code block)
    const unsigned b_lane = ((unsigned)((l >> 4) * 8 + (l & 7)) * KS
                             + (unsigned)((l >> 3) & 1) * 8) * 2;
    const unsigned C16 = 16u * KS * 2;     // +16 codes

    float acc[32];
    // 4 packed top-2 chains, one per row this lane covers (g = ra*2 + rowhalf)
    float cb_[4], cs_[4];
    #pragma unroll
    for (int i = 0; i < 4; i++) { cb_[i] = NEG_INF; cs_[i] = NEG_INF; }

    const unsigned lane_code = (unsigned)(wc * 4 + (l & 3));   // bits [2]=wc, [1:0]=q

    for (int ch = 0; ch < NCH; ch++) {
        const unsigned ub = (ch & 1) ? uB1 : uB0;

        #pragma unroll
        for (int half = 0; half < 2; half++) {
            const unsigned bbase = ub + b_lane
                                 + (unsigned)(half * 64 + wc * 32) * (KS * 2);
            #pragma unroll
            for (int s = 0; s < NSTEP; s++) {
                unsigned b0[4], b1[4];
                ldsm_x4(b0, bbase + s * 32);          // codes block cb=0 (16 codes)
                ldsm_x4(b1, bbase + C16 + s * 32);    // codes block cb=1
                if (s == 0) {
                    mma16816_z(ACC(0,0,0), aA[0][0], b0); mma16816_z(ACC(0,0,1), aA[0][0], b0 + 2);
                    mma16816_z(ACC(0,1,0), aA[0][0], b1); mma16816_z(ACC(0,1,1), aA[0][0], b1 + 2);
                    mma16816_z(ACC(1,0,0), aA[1][0], b0); mma16816_z(ACC(1,0,1), aA[1][0], b0 + 2);
                    mma16816_z(ACC(1,1,0), aA[1][0], b1); mma16816_z(ACC(1,1,1), aA[1][0], b1 + 2);
                } else {
                    mma16816(ACC(0,0,0), aA[0][s], b0); mma16816(ACC(0,0,1), aA[0][s], b0 + 2);
                    mma16816(ACC(0,1,0), aA[0][s], b1); mma16816(ACC(0,1,1), aA[0][s], b1 + 2);
                    mma16816(ACC(1,0,0), aA[1][s], b0); mma16816(ACC(1,0,1), aA[1][s], b0 + 2);
                    mma16816(ACC(1,1,0), aA[1][s], b1); mma16816(ACC(1,1,1), aA[1][s], b1 + 2);
                }
            }

            // ---- fold: quad-max (4 cols of one row) -> packed top-2 chains ----
            // code10 = ch<<5 | half<<4 | cb<<3 | wc<<2 | q
            const unsigned qb = ((unsigned)ch << 5) | ((unsigned)half << 4) | lane_code;
            #pragma unroll
            for (int ra = 0; ra < 2; ra++) {
                #pragma unroll
                for (int cbk = 0; cbk < 2; cbk++) {
                    const float* A0 = ACC(ra, cbk, 0);
                    const float* A1 = ACC(ra, cbk, 1);
                    const unsigned qc = qb | ((unsigned)cbk << 3);
                    {   // rowhalf 0
                        float qm = fmaxf(fmaxf(A0[0], A0[1]), fmaxf(A1[0], A1[1]));
                        float pv = __uint_as_float((__float_as_uint(qm) & 0xFFFFFC00u) | qc);
                        const int g = ra * 2;
                        cs_[g] = fmaxf(cs_[g], fminf(cb_[g], pv));
                        cb_[g] = fmaxf(cb_[g], pv);
                    }
                    {   // rowhalf 1
                        float qm = fmaxf(fmaxf(A0[2], A0[3]), fmaxf(A1[2], A1[3]));
                        float pv = __uint_as_float((__float_as_uint(qm) & 0xFFFFFC00u) | qc);
                        const int g = ra * 2 + 1;
                        cs_[g] = fmaxf(cs_[g], fminf(cb_[g], pv));
                        cb_[g] = fmaxf(cb_[g], pv);
                    }
                }
            }
        }

        __syncthreads();                         // all reads of buf[ch&1] done
        if (ch + 2 < NCH) {                      // prefetch chunk ch+2 into buf[ch&1]
            const unsigned ubn = (ch & 1) ? uB1 : uB0;
            const unsigned char* gBn = g_B + (size_t)(ch + 2) * TILE_BYTES;
            for (int u = tid; u < CP_UNITS; u += 256) cp_async16(ubn + u * 16, gBn + u * 16);
            cp_commit();
            cp_wait<1>();                        // chunk ch+1 landed
        } else if (ch + 1 < NCH) {
            cp_wait<0>();
        }
        __syncthreads();                         // visibility of prefetched data
    }

    // ---- per-row top-3 quads: promote chain top-2, quad-lane merge ----
    float* s_v0 = reinterpret_cast<float*>(smem_raw);            // [2][128]
    float* s_v1 = s_v0 + 256;
    float* s_v2 = s_v1 + 256;

    #pragma unroll
    for (int g = 0; g < 4; g++) {
        float tv[3];
        tv[0] = cb_[g]; tv[1] = cs_[g]; tv[2] = NEG_INF;
        merge3f_shfl(tv, 1);
        merge3f_shfl(tv, 2);
        if ((l & 3) == 0) {
            const int ra = g >> 1, rh = g & 1;
            const int row = wr * 32 + ra * 16 + rh * 8 + (l >> 2);
            const int ix  = wc * 128 + row;
            s_v0[ix] = tv[0]; s_v1[ix] = tv[1]; s_v2[ix] = tv[2];
        }
    }
    __syncthreads();

    // ---- merge col-groups, decode, exact fp32 rescore of 12 codes ----
    const size_t osz = (size_t)out_size_i;
    float lsum = 0.0f;
    if (tid < 128) {
        float tv[3];
        tv[0] = s_v0[tid]; tv[1] = s_v1[tid]; tv[2] = s_v2[tid];
        ins3f(tv, s_v0[128 + tid]);
        ins3f(tv, s_v1[128 + tid]);
        ins3f(tv, s_v2[128 + tid]);

        const int m = tile * MT + tid;
        const float4* zr = reinterpret_cast<const float4*>(z_e + (size_t)m * D_DIM);
        float4 zv[16];
        #pragma unroll
        for (int j = 0; j < 16; j++) zv[j] = zr[j];

        float bestv = NEG_INF;
        int   fin   = K_CODES;
        #pragma unroll
        for (int c3 = 0; c3 < 3; c3++) {
            const unsigned bits = __float_as_uint(tv[c3]) & 1023u;
            const int col0 = (int)(((bits >> 5) << 7) | (((bits >> 4) & 1u) << 6)
                                   | (((bits >> 2) & 1u) << 5) | (((bits >> 3) & 1u) << 4)
                                   | ((bits & 3u) << 1));
            #pragma unroll
            for (int oi = 0; oi < 4; oi++) {
                const int code = col0 + ((oi & 1) + (oi >> 1) * 8);  // +{0,1,8,9}
                const float4* er = reinterpret_cast<const float4*>(cb + (size_t)code * D_DIM);
                float s = -g_c[code];
                #pragma unroll
                for (int j = 0; j < 16; j++) {
                    float4 e = er[j];
                    s += zv[j].x * e.x + zv[j].y * e.y + zv[j].z * e.z + zv[j].w * e.w;
                }
                if (s > bestv || (s == bestv && code < fin)) { bestv = s; fin = code; }
            }
        }

        // ---- outputs ----
        const size_t MD    = (size_t)M_ROWS * D_DIM;
        const size_t base2 = MD + M_ROWS + 2;
        const float4* er = reinterpret_cast<const float4*>(cb + (size_t)fin * D_DIM);
        float4* out4 = reinterpret_cast<float4*>(out);
        float2* out2 = reinterpret_cast<float2*>(out);
        const size_t o1 = (size_t)m * D_DIM;
        const size_t o3 = base2 + (size_t)m * D_DIM;

        #pragma unroll
        for (int j = 0; j < 16; j++) {
            float4 e = er[j];
            float4 z = zv[j];
            float4 zst;
            zst.x = z.x + (e.x - z.x);
            zst.y = z.y + (e.y - z.y);
            zst.z = z.z + (e.z - z.z);
            zst.w = z.w + (e.w - z.w);
            float d0 = z.x - e.x, d1 = z.y - e.y, d2 = z.z - e.z, d3 = z.w - e.w;
            lsum += d0 * d0 + d1 * d1 + d2 * d2 + d3 * d3;
            if (o1 + (size_t)j * 4 + 4 <= osz) out4[o1 / 4 + j] = zst;
            if (o3 + (size_t)j * 4 + 4 <= osz) {
                out2[o3 / 2 + 2 * j]     = make_float2(e.x, e.y);
                out2[o3 / 2 + 2 * j + 1] = make_float2(e.z, e.w);
            }
        }
        if (MD + (size_t)m < osz) out[MD + (size_t)m] = (float)fin;
    }

    #pragma unroll
    for (int o = 16; o > 0; o >>= 1) lsum += __shfl_down_sync(0xffffffffu, lsum, o);
    if ((tid & 31) == 0) shred[w] = lsum;
    __syncthreads();
    if (tid == 0) {
        float t = 0.0f;
        #pragma unroll
        for (int i = 0; i < 8; i++) t += shred[i];
        g_partials[tile] = t;
    }
}

// ===================== finalize: vq_loss + perplexity =====================
__global__ void vq_finalize_kernel(const float* __restrict__ ema,
                                   float* __restrict__ out, int out_size_i) {
    __shared__ float red[1024];
    const size_t osz = (size_t)out_size_i;
    const int tid = threadIdx.x;

    float v = (tid < MTILES) ? g_partials[tid] : 0.0f;
    red[tid] = v;
    for (int o = 512; o > 0; o >>= 1) {
        __syncthreads();
        if (tid < o) red[tid] += red[tid + o];
    }
    __syncthreads();
    const float vq_loss = 0.25f * red[0] / (float)((size_t)M_ROWS * D_DIM);
    __syncthreads();

    float s = 0.0f;
    for (int i = tid; i < K_CODES; i += 1024) s += ema[i] + 1e-10f;
    red[tid] = s;
    for (int o = 512; o > 0; o >>= 1) {
        __syncthreads();
        if (tid < o) red[tid] += red[tid + o];
    }
    __syncthreads();
    const float S = red[0];
    __syncthreads();

    float ent = 0.0f;
    for (int i = tid; i < K_CODES; i += 1024) {
        float p = (ema[i] + 1e-10f) / S;
        ent += p * logf(p);
    }
    red[tid] = ent;
    for (int o = 512; o > 0; o >>= 1) {
        __syncthreads();
        if (tid < o) red[tid] += red[tid + o];
    }
    __syncthreads();

    if (tid == 0) {
        const size_t base = (size_t)M_ROWS * D_DIM + M_ROWS;
        if (base < osz)     out[base]     = vq_loss;
        if (base + 1 < osz) out[base + 1] = expf(-red[0]);
    }
}

extern "C" void kernel_launch(void* const* d_in, const int* in_sizes, int n_in,
                              void* d_out, int out_size) {
    const float* z_e = (const float*)d_in[0];   // (65536, 64) f32
    const float* cb  = (const float*)d_in[1];   // (4096, 64) f32
    const float* ema = (const float*)d_in[2];   // (4096,) f32
    float* out = (float*)d_out;

    cudaFuncSetAttribute(vq_mma_kernel,
                         cudaFuncAttributeMaxDynamicSharedMemorySize, SMEM_DYN);

    vq_prep_c<<<K_CODES / 8, 256>>>(cb);
    vq_prep_A<<<M_ROWS / 8, 256>>>(z_e);
    vq_prep_B<<<K_CODES / 8, 256>>>(cb);
    vq_mma_kernel<<<MTILES, 256, SMEM_DYN>>>(out, z_e, cb, out_size);
    vq_finalize_kernel<<<1, 1024>>>(ema, out, out_size);
}